// round 1
// baseline (speedup 1.0000x reference)
#include <cuda_runtime.h>

// ContrastivePredictionLoss:
//   errors[b] = mean(|pred_mean[b] - targets[b]|)   over 4*256*256 = 262144 elems
//   unc[b]    = mean(pred_std[b])
//   loss      = sum_{i<j} max( (err_i>err_j ? unc_j-unc_i : unc_i-unc_j) + 1, 0 ) / 2016
//
// Stage A: 64 batches x 32 blocks, deterministic block-level partial sums.
// Stage B: single block reduces partials + computes 64x64 pairwise hinge.

#define NB 64
#define ELEMS_PER_BATCH (4 * 256 * 256)      // 262144
#define BLOCKS_PER_BATCH 32
#define THREADS_A 256
#define ELEMS_PER_BLOCK (ELEMS_PER_BATCH / BLOCKS_PER_BATCH)   // 8192
#define VECS_PER_BLOCK (ELEMS_PER_BLOCK / 4)                   // 2048 float4
#define VECS_PER_THREAD (VECS_PER_BLOCK / THREADS_A)           // 8

// Scratch: partial sums per block (allocation-free __device__ globals).
__device__ float g_part_err[NB * BLOCKS_PER_BATCH];
__device__ float g_part_unc[NB * BLOCKS_PER_BATCH];

__global__ __launch_bounds__(THREADS_A)
void cpl_reduce_kernel(const float4* __restrict__ pm,
                       const float4* __restrict__ ps,
                       const float4* __restrict__ tg) {
    const int blk = blockIdx.x;                      // b * 32 + chunk
    const int tid = threadIdx.x;
    const long base = (long)blk * VECS_PER_BLOCK;

    float se = 0.0f;   // sum |pm - tg|
    float su = 0.0f;   // sum ps

    #pragma unroll
    for (int i = 0; i < VECS_PER_THREAD; i++) {
        const long idx = base + (long)i * THREADS_A + tid;
        float4 m = pm[idx];
        float4 t = tg[idx];
        float4 s = ps[idx];
        se += fabsf(m.x - t.x) + fabsf(m.y - t.y)
            + fabsf(m.z - t.z) + fabsf(m.w - t.w);
        su += s.x + s.y + s.z + s.w;
    }

    // Warp reduce (deterministic shuffle tree)
    #pragma unroll
    for (int off = 16; off > 0; off >>= 1) {
        se += __shfl_down_sync(0xFFFFFFFFu, se, off);
        su += __shfl_down_sync(0xFFFFFFFFu, su, off);
    }

    __shared__ float s_se[THREADS_A / 32];
    __shared__ float s_su[THREADS_A / 32];
    const int wid = tid >> 5;
    const int lid = tid & 31;
    if (lid == 0) { s_se[wid] = se; s_su[wid] = su; }
    __syncthreads();

    if (wid == 0) {
        se = (lid < THREADS_A / 32) ? s_se[lid] : 0.0f;
        su = (lid < THREADS_A / 32) ? s_su[lid] : 0.0f;
        #pragma unroll
        for (int off = 4; off > 0; off >>= 1) {
            se += __shfl_down_sync(0xFFFFFFFFu, se, off);
            su += __shfl_down_sync(0xFFFFFFFFu, su, off);
        }
        if (lid == 0) {
            g_part_err[blk] = se;
            g_part_unc[blk] = su;
        }
    }
}

#define THREADS_B 128

__global__ __launch_bounds__(THREADS_B)
void cpl_finalize_kernel(float* __restrict__ out) {
    __shared__ float errs[NB];
    __shared__ float uncs[NB];
    const int tid = threadIdx.x;

    // Per-batch reduction of 32 partials (thread b handles batch b; fixed order).
    if (tid < NB) {
        float se = 0.0f, su = 0.0f;
        #pragma unroll
        for (int c = 0; c < BLOCKS_PER_BATCH; c++) {
            se += g_part_err[tid * BLOCKS_PER_BATCH + c];
            su += g_part_unc[tid * BLOCKS_PER_BATCH + c];
        }
        const float inv = 1.0f / (float)ELEMS_PER_BATCH;
        errs[tid] = se * inv;
        uncs[tid] = su * inv;
    }
    __syncthreads();

    // Pairwise hinge over upper triangle (i < j), fixed iteration order.
    float acc = 0.0f;
    for (int p = tid; p < NB * NB; p += THREADS_B) {
        const int i = p >> 6;      // p / 64
        const int j = p & 63;      // p % 64
        if (i < j) {
            const float d = ((errs[i] > errs[j]) ? (uncs[j] - uncs[i])
                                                 : (uncs[i] - uncs[j])) + 1.0f;
            acc += fmaxf(d, 0.0f);
        }
    }

    // Block reduce (deterministic)
    #pragma unroll
    for (int off = 16; off > 0; off >>= 1)
        acc += __shfl_down_sync(0xFFFFFFFFu, acc, off);

    __shared__ float s_acc[THREADS_B / 32];
    const int wid = tid >> 5;
    const int lid = tid & 31;
    if (lid == 0) s_acc[wid] = acc;
    __syncthreads();

    if (tid == 0) {
        float total = 0.0f;
        #pragma unroll
        for (int w = 0; w < THREADS_B / 32; w++) total += s_acc[w];
        const int num_pairs = NB * (NB - 1) / 2;   // 2016
        out[0] = total / (float)num_pairs;
    }
}

extern "C" void kernel_launch(void* const* d_in, const int* in_sizes, int n_in,
                              void* d_out, int out_size) {
    const float4* pm = (const float4*)d_in[0];   // pred_mean
    const float4* ps = (const float4*)d_in[1];   // pred_std
    const float4* tg = (const float4*)d_in[2];   // targets
    float* out = (float*)d_out;

    cpl_reduce_kernel<<<NB * BLOCKS_PER_BATCH, THREADS_A>>>(pm, ps, tg);
    cpl_finalize_kernel<<<1, THREADS_B>>>(out);
}